// round 3
// baseline (speedup 1.0000x reference)
#include <cuda_runtime.h>
#include <cstdint>

// Shapes (fixed by the problem):
//   x      [B=4][Cin=64][12][12][12][12]
//   weight [Cin=64][Cout=64][3][3][3][3]
//   bias   [64]
//   out    [B=4][Cout=64][25][25][25][25]   (z = 2m+p, stride 2, K=3)

#define B_      4
#define CIN     64
#define COUT    64
#define LDIM    12
#define ODIM    25
#define NTAPS   81            // 3^4
#define XCH_STRIDE (12*12*12*12)      // 20736
#define OCH_STRIDE (25*25*25*25)      // 390625

// Pre-transposed weights: wt[tap][i][o], o contiguous. 81*64*64 floats = 1.33 MB
__device__ float g_wt[NTAPS * CIN * COUT];

__global__ void wt_prep_kernel(const float* __restrict__ w) {
    int idx = blockIdx.x * 256 + threadIdx.x;
    if (idx >= NTAPS * CIN * COUT) return;
    int t = idx / (CIN * COUT);
    int r = idx - t * (CIN * COUT);
    int i = r >> 6;
    int o = r & 63;
    // w layout: [i][o][k1][k2][k3][k4]  ->  linear (i*64 + o)*81 + t
    g_wt[idx] = w[(i * COUT + o) * NTAPS + t];
}

__global__ __launch_bounds__(128)
void ct4d_kernel(const float* __restrict__ x,
                 const float* __restrict__ bias,
                 float* __restrict__ out) {
    // parity class
    const int pc = blockIdx.y;
    const int p1 = (pc >> 3) & 1, p2 = (pc >> 2) & 1, p3 = (pc >> 1) & 1, p4 = pc & 1;
    const int n1 = p1 ? 12 : 13, n2 = p2 ? 12 : 13, n3 = p3 ? 12 : 13, n4 = p4 ? 12 : 13;
    const int csz = n1 * n2 * n3 * n4;
    if (blockIdx.x * 128 >= csz) return;   // uniform over block: safe before syncs

    const int b   = blockIdx.z;
    const int lin = blockIdx.x * 128 + threadIdx.x;
    const bool in_range = (lin < csz);

    int l = in_range ? lin : 0;
    const int m4 = l % n4; l /= n4;
    const int m3 = l % n3; l /= n3;
    const int m2 = l % n2; l /= n2;
    const int m1 = l;

    // 16 KB weight stage: [i=64][16 x ulonglong2] = 64x64 fp32
    __shared__ ulonglong2 sw[CIN * 16];

    // accumulators: 32 packed f32x2 pairs over Cout, init with bias
    unsigned long long acc[32];
    {
        const unsigned long long* bu = (const unsigned long long*)bias;
        #pragma unroll
        for (int q = 0; q < 32; q++) acc[q] = bu[q];
    }

    const int t1max = p1 ? 0 : 1;
    const int t2max = p2 ? 0 : 1;
    const int t3max = p3 ? 0 : 1;
    const int t4max = p4 ? 0 : 1;

    for (int t1 = 0; t1 <= t1max; t1++) {
        const int k1 = p1 + 2 * t1;
        const int l1 = m1 - t1;
        for (int t2 = 0; t2 <= t2max; t2++) {
            const int k2 = p2 + 2 * t2;
            const int l2 = m2 - t2;
            for (int t3 = 0; t3 <= t3max; t3++) {
                const int k3 = p3 + 2 * t3;
                const int l3 = m3 - t3;
                for (int t4 = 0; t4 <= t4max; t4++) {
                    const int k4 = p4 + 2 * t4;
                    const int l4 = m4 - t4;
                    const int tap = ((k1 * 3 + k2) * 3 + k3) * 3 + k4;

                    // stage 64x64 weight slice (all threads participate)
                    __syncthreads();
                    {
                        const float4* src = (const float4*)(g_wt + tap * (CIN * COUT));
                        float4* dst = (float4*)sw;
                        #pragma unroll
                        for (int s = 0; s < 8; s++)
                            dst[threadIdx.x + s * 128] = src[threadIdx.x + s * 128];
                    }
                    __syncthreads();

                    const bool act = in_range &&
                        ((unsigned)l1 < LDIM) && ((unsigned)l2 < LDIM) &&
                        ((unsigned)l3 < LDIM) && ((unsigned)l4 < LDIM);
                    if (act) {
                        const float* xp = x + (size_t)b * CIN * XCH_STRIDE
                                        + ((((size_t)l1 * 12 + l2) * 12 + l3) * 12 + l4);
                        #pragma unroll 2
                        for (int i = 0; i < CIN; i++) {
                            const float xv = __ldg(xp + (size_t)i * XCH_STRIDE);
                            unsigned long long xx;
                            asm("mov.b64 %0, {%1, %1};" : "=l"(xx) : "f"(xv));
                            const ulonglong2* wr = sw + i * 16;
                            #pragma unroll
                            for (int j = 0; j < 16; j++) {
                                const ulonglong2 wv = wr[j];
                                asm("fma.rn.f32x2 %0, %1, %2, %0;"
                                    : "+l"(acc[2 * j])     : "l"(xx), "l"(wv.x));
                                asm("fma.rn.f32x2 %0, %1, %2, %0;"
                                    : "+l"(acc[2 * j + 1]) : "l"(xx), "l"(wv.y));
                            }
                        }
                    }
                }
            }
        }
    }

    if (in_range) {
        const int z1 = 2 * m1 + p1;
        const int z2 = 2 * m2 + p2;
        const int z3 = 2 * m3 + p3;
        const int z4 = 2 * m4 + p4;
        const size_t sp = ((((size_t)z1 * ODIM + z2) * ODIM + z3) * ODIM) + z4;
        float* op = out + (size_t)b * COUT * OCH_STRIDE + sp;
        #pragma unroll
        for (int q = 0; q < 32; q++) {
            const unsigned long long a = acc[q];
            op[(size_t)(2 * q)     * OCH_STRIDE] = __uint_as_float((unsigned)(a & 0xffffffffu));
            op[(size_t)(2 * q + 1) * OCH_STRIDE] = __uint_as_float((unsigned)(a >> 32));
        }
    }
}

extern "C" void kernel_launch(void* const* d_in, const int* in_sizes, int n_in,
                              void* d_out, int out_size) {
    const float* x    = (const float*)d_in[0];
    const float* w    = (const float*)d_in[1];
    const float* bias = (const float*)d_in[2];
    float* out        = (float*)d_out;

    // 1) transpose weights into [tap][i][o]
    const int wtot = NTAPS * CIN * COUT;  // 331776
    wt_prep_kernel<<<(wtot + 255) / 256, 256>>>(w);

    // 2) main gather kernel: grid.x covers the largest parity class (13^4 = 28561)
    dim3 grid((28561 + 127) / 128, 16, B_);
    ct4d_kernel<<<grid, 128>>>(x, bias, out);
}

// round 4
// speedup vs baseline: 1.0714x; 1.0714x over previous
#include <cuda_runtime.h>
#include <cstdint>

// Shapes (fixed):
//   x      [B=4][Cin=64][12][12][12][12]
//   weight [Cin=64][Cout=64][3][3][3][3]
//   bias   [64]
//   out    [B=4][Cout=64][25][25][25][25]   (z = 2m+p, stride 2, K=3)

#define B_      4
#define CIN     64
#define COUT    64
#define LDIM    12
#define ODIM    25
#define NTAPS   81
#define XCH_STRIDE (12*12*12*12)      // 20736
#define OCH_STRIDE (25*25*25*25)      // 390625

// Pre-transposed weights: wt[tap][i][o], o contiguous. 81*64*64 floats = 1.33 MB
__device__ float g_wt[NTAPS * CIN * COUT];

__global__ void wt_prep_kernel(const float* __restrict__ w) {
    int idx = blockIdx.x * 256 + threadIdx.x;
    if (idx >= NTAPS * CIN * COUT) return;
    int t = idx / (CIN * COUT);
    int r = idx - t * (CIN * COUT);
    int i = r >> 6;
    int o = r & 63;
    g_wt[idx] = w[(i * COUT + o) * NTAPS + t];
}

__global__ __launch_bounds__(128, 2)
void ct4d_kernel(const float* __restrict__ x,
                 const float* __restrict__ bias,
                 float* __restrict__ out) {
    // parity class
    const int pc = blockIdx.y;
    const int p1 = (pc >> 3) & 1, p2 = (pc >> 2) & 1, p3 = (pc >> 1) & 1, p4 = pc & 1;
    const int n1 = p1 ? 12 : 13, n2 = p2 ? 12 : 13, n3 = p3 ? 12 : 13, n4 = p4 ? 12 : 13;
    const int n1h = (n1 + 1) >> 1;                 // split m1 range in half
    const int cszh = n1h * n2 * n3 * n4;
    if (blockIdx.x * 128 >= cszh) return;          // uniform over block

    const int b   = blockIdx.z;
    const int lin = blockIdx.x * 128 + threadIdx.x;
    const bool in_range = (lin < cszh);

    int l = in_range ? lin : 0;
    const int m4  = l % n4; l /= n4;
    const int m3  = l % n3; l /= n3;
    const int m2  = l % n2; l /= n2;
    const int m1a = l;
    const int m1b = m1a + n1h;
    const bool validB = in_range && (m1b < n1);

    // 16 KB weight stage: [i=64][16 x ulonglong2] = 64x64 fp32
    __shared__ ulonglong2 sw[CIN * 16];

    // two output points, each 32 packed f32x2 accumulators over Cout
    unsigned long long accA[32], accB[32];
    {
        const unsigned long long* bu = (const unsigned long long*)bias;
        #pragma unroll
        for (int q = 0; q < 32; q++) { accA[q] = bu[q]; accB[q] = bu[q]; }
    }

    const int t1max = p1 ? 0 : 1;
    const int t2max = p2 ? 0 : 1;
    const int t3max = p3 ? 0 : 1;
    const int t4max = p4 ? 0 : 1;

    const float* xbase = x + (size_t)b * CIN * XCH_STRIDE;

    for (int t1 = 0; t1 <= t1max; t1++) {
        const int k1  = p1 + 2 * t1;
        const int l1a = m1a - t1;
        const int l1b = m1b - t1;
        for (int t2 = 0; t2 <= t2max; t2++) {
            const int k2 = p2 + 2 * t2;
            const int l2 = m2 - t2;
            for (int t3 = 0; t3 <= t3max; t3++) {
                const int k3 = p3 + 2 * t3;
                const int l3 = m3 - t3;
                for (int t4 = 0; t4 <= t4max; t4++) {
                    const int k4 = p4 + 2 * t4;
                    const int l4 = m4 - t4;
                    const int tap = ((k1 * 3 + k2) * 3 + k3) * 3 + k4;

                    // stage the 64x64 weight slice (all threads participate)
                    __syncthreads();
                    {
                        const float4* src = (const float4*)(g_wt + tap * (CIN * COUT));
                        float4* dst = (float4*)sw;
                        #pragma unroll
                        for (int s = 0; s < 8; s++)
                            dst[threadIdx.x + s * 128] = src[threadIdx.x + s * 128];
                    }
                    __syncthreads();

                    const bool c234 = in_range &&
                        ((unsigned)l2 < LDIM) && ((unsigned)l3 < LDIM) && ((unsigned)l4 < LDIM);
                    const bool actA = c234 && ((unsigned)l1a < LDIM);
                    const bool actB = c234 && validB && ((unsigned)l1b < LDIM);
                    if (actA | actB) {
                        const int sp234 = ((l2 * 12 + l3) * 12 + l4);
                        const float* xpA = xbase + (size_t)(l1a * 1728 + sp234);
                        const float* xpB = xbase + (size_t)(l1b * 1728 + sp234);
                        #pragma unroll 2
                        for (int i = 0; i < CIN; i++) {
                            const float xvA = actA ? __ldg(xpA + (size_t)i * XCH_STRIDE) : 0.0f;
                            const float xvB = actB ? __ldg(xpB + (size_t)i * XCH_STRIDE) : 0.0f;
                            unsigned long long xxA, xxB;
                            asm("mov.b64 %0, {%1, %1};" : "=l"(xxA) : "f"(xvA));
                            asm("mov.b64 %0, {%1, %1};" : "=l"(xxB) : "f"(xvB));
                            const ulonglong2* wr = sw + i * 16;
                            #pragma unroll
                            for (int j = 0; j < 16; j++) {
                                const ulonglong2 wv = wr[j];
                                asm("fma.rn.f32x2 %0, %1, %2, %0;"
                                    : "+l"(accA[2 * j])     : "l"(xxA), "l"(wv.x));
                                asm("fma.rn.f32x2 %0, %1, %2, %0;"
                                    : "+l"(accA[2 * j + 1]) : "l"(xxA), "l"(wv.y));
                                asm("fma.rn.f32x2 %0, %1, %2, %0;"
                                    : "+l"(accB[2 * j])     : "l"(xxB), "l"(wv.x));
                                asm("fma.rn.f32x2 %0, %1, %2, %0;"
                                    : "+l"(accB[2 * j + 1]) : "l"(xxB), "l"(wv.y));
                            }
                        }
                    }
                }
            }
        }
    }

    if (in_range) {
        const int z2 = 2 * m2 + p2, z3 = 2 * m3 + p3, z4 = 2 * m4 + p4;
        const size_t sp234 = (((size_t)z2 * ODIM + z3) * ODIM) + z4;
        float* obase = out + (size_t)b * COUT * OCH_STRIDE;
        {
            const size_t sp = (size_t)(2 * m1a + p1) * (ODIM * ODIM * ODIM) + sp234;
            float* op = obase + sp;
            #pragma unroll
            for (int q = 0; q < 32; q++) {
                const unsigned long long a = accA[q];
                op[(size_t)(2 * q)     * OCH_STRIDE] = __uint_as_float((unsigned)(a & 0xffffffffu));
                op[(size_t)(2 * q + 1) * OCH_STRIDE] = __uint_as_float((unsigned)(a >> 32));
            }
        }
        if (validB) {
            const size_t sp = (size_t)(2 * m1b + p1) * (ODIM * ODIM * ODIM) + sp234;
            float* op = obase + sp;
            #pragma unroll
            for (int q = 0; q < 32; q++) {
                const unsigned long long a = accB[q];
                op[(size_t)(2 * q)     * OCH_STRIDE] = __uint_as_float((unsigned)(a & 0xffffffffu));
                op[(size_t)(2 * q + 1) * OCH_STRIDE] = __uint_as_float((unsigned)(a >> 32));
            }
        }
    }
}

extern "C" void kernel_launch(void* const* d_in, const int* in_sizes, int n_in,
                              void* d_out, int out_size) {
    const float* x    = (const float*)d_in[0];
    const float* w    = (const float*)d_in[1];
    const float* bias = (const float*)d_in[2];
    float* out        = (float*)d_out;

    const int wtot = NTAPS * CIN * COUT;  // 331776
    wt_prep_kernel<<<(wtot + 255) / 256, 256>>>(w);

    // grid.x covers the largest half-class: ceil(13/2)*13^3 = 15379 points
    dim3 grid((15379 + 127) / 128, 16, B_);
    ct4d_kernel<<<grid, 128>>>(x, bias, out);
}